// round 14
// baseline (speedup 1.0000x reference)
#include <cuda_runtime.h>
#include <cuda_bf16.h>
#include <math.h>
#include <limits.h>

#define NN 100000
#define EE 3200000
#define FF 128
#define UU 1000
#define DETECT_N 262144

#define FMA_F32X2(d, a, b, c) \
    asm("fma.rn.f32x2 %0, %1, %2, %3;" : "=l"(d) : "l"(a), "l"(b), "l"(c))
#define PACK2_F32(out, v) \
    asm("mov.b64 %0, {%1, %1};" : "=l"(out) : "r"(v))

// Scratch (device globals) — referenced ONLY inside kernels (never as launch args!)
__device__ float          g_A  [(long long)NN * FF];
__device__ float          g_H  [(long long)NN * FF];
__device__ __nv_bfloat16  g_Xh [(long long)NN * FF];
__device__ float g_inv[NN];
__device__ int   g_deg[NN];
__device__ int   g_mask[NN];
__device__ int   g_list[NN];
__device__ int   g_off[NN];
__device__ int   g_cur[NN];   // pre-initialized to off for masked nodes
__device__ int   g_csr[EE];
__device__ int   g_cnt;
__device__ int   g_total;
__device__ int   g_is32;      // monotonic: set once, never reset

__device__ __forceinline__ int edge_at(const void* p, long long i) {
    return g_is32 ? ((const int*)p)[i] : (int)((const long long*)p)[i];
}

__device__ __forceinline__ int2 edge_pair(const void* p, long long i2) {
    if (g_is32) {
        return ((const int2*)p)[i2];
    } else {
        longlong2 v = ((const longlong2*)p)[i2];
        return make_int2((int)v.x, (int)v.y);
    }
}

// ---------------------------------------------------------------------------
// node init + dtype detect (main stream; small). grid = DETECT_N/256 blocks.
__global__ void k_init_nodes(const int* __restrict__ e32) {
    int i = blockIdx.x * 256 + threadIdx.x;
    if (i < NN) {
        g_deg[i] = 0;
        g_mask[i] = (i < UU) ? 1 : 0;
    }
    if (i == 0) { g_cnt = 0; g_total = 0; }
    if (i < DETECT_N && e32[2 * i + 1] != 0) g_is32 = 1;
}

// bf16 conversion of x (side stream; only needed by agg1).
__global__ void k_tobf16(const float* __restrict__ x) {
    long long i = (long long)blockIdx.x * 256 + threadIdx.x;
    float4 v = ((const float4*)x)[i];
    __nv_bfloat162 a = __floats2bfloat162_rn(v.x, v.y);
    __nv_bfloat162 b = __floats2bfloat162_rn(v.z, v.w);
    uint2 u; u.x = *(unsigned*)&a; u.y = *(unsigned*)&b;
    ((uint2*)g_Xh)[i] = u;
}

// deg+mask: 2 edges per thread, dst column only; src fetched lazily (~1%).
__global__ void k_deg_mask(const void* __restrict__ eS, const void* __restrict__ eD,
                           long long dOff2) {
    int t = blockIdx.x * 256 + threadIdx.x;
    if (t >= EE / 2) return;
    int2 d = edge_pair(eD, dOff2 + t);
    if ((unsigned)d.x < NN) {
        atomicAdd(&g_deg[d.x], 1);
        if (d.x < UU) {
            int src = edge_at(eS, 2LL * t);
            if ((unsigned)src < NN) g_mask[src] = 1;
        }
    }
    if ((unsigned)d.y < NN) {
        atomicAdd(&g_deg[d.y], 1);
        if (d.y < UU) {
            int src = edge_at(eS, 2LL * t + 1);
            if ((unsigned)src < NN) g_mask[src] = 1;
        }
    }
}

// inv-sqrt + compact + bucket allocation (warp-aggregated atomics)
// + fused cursor init (cur = off for masked nodes).
__global__ void k_inv_compact() {
    int i = blockIdx.x * 256 + threadIdx.x;
    int lane = threadIdx.x & 31;
    bool inb = (i < NN);
    int d = inb ? g_deg[i] : 0;
    if (inb) g_inv[i] = rsqrtf((float)d + 1.0f);
    bool active = inb && g_mask[i];
    unsigned ballot = __ballot_sync(0xFFFFFFFFu, active);
    int total = __popc(ballot);
    int myidx = __popc(ballot & ((1u << lane) - 1));
    int dv = active ? d : 0;
    int v = dv;
    #pragma unroll
    for (int o = 1; o < 32; o <<= 1) {
        int t = __shfl_up_sync(0xFFFFFFFFu, v, o);
        if (lane >= o) v += t;
    }
    int excl = v - dv;
    int wsum = __shfl_sync(0xFFFFFFFFu, v, 31);
    int baseCnt = 0, baseOff = 0;
    if (total > 0 && lane == 0) {
        baseCnt = atomicAdd(&g_cnt, total);
        baseOff = atomicAdd(&g_total, wsum);
    }
    baseCnt = __shfl_sync(0xFFFFFFFFu, baseCnt, 0);
    baseOff = __shfl_sync(0xFFFFFFFFu, baseOff, 0);
    if (active) {
        int off = baseOff + excl;
        g_list[baseCnt + myidx] = i;
        g_off[i] = off;
        g_cur[i] = off;
    }
}

// fill: mask-gated single atomic (cur pre-initialized to off).
__global__ void k_fill(const void* __restrict__ eS, const void* __restrict__ eD,
                       long long dOff2) {
    int t = blockIdx.x * 256 + threadIdx.x;
    if (t >= EE / 2) return;
    int2 d = edge_pair(eD, dOff2 + t);
    if ((unsigned)d.x < NN && g_mask[d.x]) {
        int pos = atomicAdd(&g_cur[d.x], 1);
        if ((unsigned)pos < EE) {
            int src = edge_at(eS, 2LL * t);
            g_csr[pos] = ((unsigned)src < NN) ? src : 0;
        }
    }
    if ((unsigned)d.y < NN && g_mask[d.y]) {
        int pos = atomicAdd(&g_cur[d.y], 1);
        if ((unsigned)pos < EE) {
            int src = edge_at(eS, 2LL * t + 1);
            g_csr[pos] = ((unsigned)src < NN) ? src : 0;
        }
    }
}

// ---------------------------------------------------------------------------
// Layer-1 aggregation: warp per compact row; bf16 uint2 gathers, fp32 accum.
__device__ __forceinline__ void bf16_fma(float4& acc, float c, uint2 u) {
    float2 f0 = __bfloat1622float2(*(__nv_bfloat162*)&u.x);
    float2 f1 = __bfloat1622float2(*(__nv_bfloat162*)&u.y);
    acc.x += c * f0.x; acc.y += c * f0.y;
    acc.z += c * f1.x; acc.w += c * f1.y;
}

__global__ void k_agg1(const float* __restrict__ x) {
    int w = (blockIdx.x * 256 + threadIdx.x) >> 5;
    int lane = threadIdx.x & 31;
    if (w >= g_cnt) return;
    int row = g_list[w];
    float invr = g_inv[row];
    float4 acc = ((const float4*)(x + (long long)row * FF))[lane];
    float s = invr * invr;
    acc.x *= s; acc.y *= s; acc.z *= s; acc.w *= s;
    int beg = g_off[row], end = beg + g_deg[row];
    int j = beg;
    for (; j + 4 <= end; j += 4) {
        int s0 = g_csr[j], s1 = g_csr[j + 1], s2 = g_csr[j + 2], s3 = g_csr[j + 3];
        float c0 = g_inv[s0] * invr, c1 = g_inv[s1] * invr;
        float c2 = g_inv[s2] * invr, c3 = g_inv[s3] * invr;
        uint2 u0 = *(const uint2*)(g_Xh + (long long)s0 * FF + lane * 4);
        uint2 u1 = *(const uint2*)(g_Xh + (long long)s1 * FF + lane * 4);
        uint2 u2 = *(const uint2*)(g_Xh + (long long)s2 * FF + lane * 4);
        uint2 u3 = *(const uint2*)(g_Xh + (long long)s3 * FF + lane * 4);
        bf16_fma(acc, c0, u0); bf16_fma(acc, c1, u1);
        bf16_fma(acc, c2, u2); bf16_fma(acc, c3, u3);
    }
    for (; j < end; j++) {
        int src = g_csr[j];
        float c = g_inv[src] * invr;
        uint2 u = *(const uint2*)(g_Xh + (long long)src * FF + lane * 4);
        bf16_fma(acc, c, u);
    }
    ((float4*)(g_A + (long long)row * FF))[lane] = acc;
}

// Layer-2 aggregation: warp per dst row < UU; fp32 (tiny).
__global__ void k_agg2() {
    int w = (blockIdx.x * 256 + threadIdx.x) >> 5;
    int lane = threadIdx.x & 31;
    if (w >= UU) return;
    int row = w;
    float invr = g_inv[row];
    float4 acc = ((const float4*)(g_H + (long long)row * FF))[lane];
    float s = invr * invr;
    acc.x *= s; acc.y *= s; acc.z *= s; acc.w *= s;
    int beg = g_off[row], end = beg + g_deg[row];
    int j = beg;
    for (; j + 2 <= end; j += 2) {
        int s0 = g_csr[j], s1 = g_csr[j + 1];
        float c0 = g_inv[s0] * invr, c1 = g_inv[s1] * invr;
        float4 v0 = ((const float4*)(g_H + (long long)s0 * FF))[lane];
        float4 v1 = ((const float4*)(g_H + (long long)s1 * FF))[lane];
        acc.x += c0 * v0.x + c1 * v1.x;
        acc.y += c0 * v0.y + c1 * v1.y;
        acc.z += c0 * v0.z + c1 * v1.z;
        acc.w += c0 * v0.w + c1 * v1.w;
    }
    for (; j < end; j++) {
        int src = g_csr[j];
        float c = g_inv[src] * invr;
        float4 v = ((const float4*)(g_H + (long long)src * FF))[lane];
        acc.x += c * v.x; acc.y += c * v.y; acc.z += c * v.z; acc.w += c * v.w;
    }
    ((float4*)(g_A + (long long)row * FF))[lane] = acc;
}

// ---------------------------------------------------------------------------
// Fused GEMM + bias + ELU: 64 rows/block, 4x8 tile, FFMA2 (f32x2) mainloop.
__global__ void k_gemm_fused(const float* __restrict__ W, const float* __restrict__ bias,
                             float* __restrict__ outp, int layer) {
    __shared__ float Ws[32 * 128];
    __shared__ float XsT[32 * 68];
    __shared__ int   rlist[64];
    __shared__ int   s_n;

    int tid = threadIdx.x;
    if (tid == 0) s_n = (layer == 1) ? g_cnt : UU;
    __syncthreads();
    int n = s_n;
    int base = blockIdx.x * 64;
    if (base >= n) return;

    if (tid < 64) {
        int gr = base + tid;
        rlist[tid] = (gr < n) ? ((layer == 1) ? g_list[gr] : gr) : -1;
    }
    float* O = (layer == 1) ? g_H : outp;

    int tx = tid & 15, ty = tid >> 4;
    unsigned long long acc2[4][4];
    #pragma unroll
    for (int i = 0; i < 4; i++)
        #pragma unroll
        for (int j = 0; j < 4; j++) acc2[i][j] = 0ULL;
    __syncthreads();

    for (int kc = 0; kc < 128; kc += 32) {
        #pragma unroll 4
        for (int idx = tid; idx < 4096; idx += 256)
            Ws[idx] = W[(kc + (idx >> 7)) * 128 + (idx & 127)];
        #pragma unroll 4
        for (int idx = tid; idx < 2048; idx += 256) {
            int r = idx >> 5, c = idx & 31;
            int grow = rlist[r];
            XsT[c * 68 + r] = (grow >= 0) ? g_A[(long long)grow * FF + kc + c] : 0.0f;
        }
        __syncthreads();

        #pragma unroll
        for (int k = 0; k < 32; k++) {
            float4 a = *(const float4*)&XsT[k * 68 + ty * 4];
            ulonglong2 w0 = *(const ulonglong2*)&Ws[k * 128 + tx * 4];
            ulonglong2 w1 = *(const ulonglong2*)&Ws[k * 128 + 64 + tx * 4];
            unsigned long long bv2[4] = {w0.x, w0.y, w1.x, w1.y};
            unsigned au[4] = {__float_as_uint(a.x), __float_as_uint(a.y),
                              __float_as_uint(a.z), __float_as_uint(a.w)};
            #pragma unroll
            for (int i = 0; i < 4; i++) {
                unsigned long long a2;
                PACK2_F32(a2, au[i]);
                #pragma unroll
                for (int j = 0; j < 4; j++)
                    FMA_F32X2(acc2[i][j], a2, bv2[j], acc2[i][j]);
            }
        }
        __syncthreads();
    }

    float bj[8];
    #pragma unroll
    for (int q = 0; q < 4; q++) {
        bj[q]     = __ldg(&bias[tx * 4 + q]);
        bj[4 + q] = __ldg(&bias[64 + tx * 4 + q]);
    }

    #pragma unroll
    for (int i = 0; i < 4; i++) {
        int gr = base + ty * 4 + i;
        if (gr < n) {
            int grow = rlist[ty * 4 + i];
            float* o = O + (long long)grow * FF;
            float r0[4], r1[4];
            #pragma unroll
            for (int j = 0; j < 4; j++) {
                unsigned lo, hi;
                asm("mov.b64 {%0, %1}, %2;" : "=r"(lo), "=r"(hi) : "l"(acc2[i][j]));
                float e0 = __uint_as_float(lo), e1 = __uint_as_float(hi);
                if (j < 2) {
                    float v = e0 + bj[2 * j];
                    r0[2 * j] = (v > 0.0f) ? v : expm1f(v);
                    v = e1 + bj[2 * j + 1];
                    r0[2 * j + 1] = (v > 0.0f) ? v : expm1f(v);
                } else {
                    float v = e0 + bj[2 * j];
                    r1[2 * (j - 2)] = (v > 0.0f) ? v : expm1f(v);
                    v = e1 + bj[2 * j + 1];
                    r1[2 * (j - 2) + 1] = (v > 0.0f) ? v : expm1f(v);
                }
            }
            *(float4*)&o[tx * 4]      = *(float4*)&r0[0];
            *(float4*)&o[64 + tx * 4] = *(float4*)&r1[0];
        }
    }
}

// ---------------------------------------------------------------------------
extern "C" void kernel_launch(void* const* d_in, const int* in_sizes, int n_in,
                              void* d_out, int out_size) {
    const float *x = 0, *W1 = 0, *b1 = 0, *W2 = 0, *b2 = 0;
    const void *eA = 0, *eB = 0;
    long long dOff = 0;
    for (int i = 0; i < n_in; i++) {
        long long s = in_sizes[i];
        if (s == (long long)NN * FF)      x = (const float*)d_in[i];
        else if (s == 2LL * EE)           eA = d_in[i];
        else if (s == (long long)EE)     { if (!eA) eA = d_in[i]; else eB = d_in[i]; }
        else if (s == FF * FF)           { if (!W1) W1 = (const float*)d_in[i];
                                           else     W2 = (const float*)d_in[i]; }
        else if (s == FF)                { if (!b1) b1 = (const float*)d_in[i];
                                           else     b2 = (const float*)d_in[i]; }
    }
    if (!eB) { eB = eA; dOff = EE; }
    float* out = (float*)d_out;
    long long dOff2 = dOff / 2;

    const int e2grid = (EE / 2 + 255) / 256;
    const int ngrid = (NN + 255) / 256;

    // side stream + events (created once; host-side objects, no device alloc)
    static cudaStream_t sB = 0;
    static cudaEvent_t evFork = 0, evJoin = 0;
    if (!sB) {
        cudaStreamCreateWithFlags(&sB, cudaStreamNonBlocking);
        cudaEventCreateWithFlags(&evFork, cudaEventDisableTiming);
        cudaEventCreateWithFlags(&evJoin, cudaEventDisableTiming);
    }

    // fork side branch: bf16 conversion + tail memcpy (independent of CSR chain)
    cudaEventRecord(evFork, 0);
    cudaStreamWaitEvent(sB, evFork, 0);
    k_tobf16<<<(NN * FF / 4) / 256, 256, 0, sB>>>(x);
    cudaMemcpyAsync(out + (long long)UU * FF, x + (long long)UU * FF,
                    (size_t)(NN - UU) * FF * sizeof(float),
                    cudaMemcpyDeviceToDevice, sB);
    cudaEventRecord(evJoin, sB);

    // main chain: CSR build
    k_init_nodes<<<DETECT_N / 256, 256>>>((const int*)eA);
    k_deg_mask<<<e2grid, 256>>>(eA, eB, dOff2);
    k_inv_compact<<<ngrid, 256>>>();
    k_fill<<<e2grid, 256>>>(eA, eB, dOff2);

    // join before agg1 (needs g_Xh; memcpy joins here too — out tail untouched after)
    cudaStreamWaitEvent(0, evJoin, 0);

    // layer 1: bf16 gather-aggregate over S, fused GEMM+bias+ELU -> g_H
    k_agg1<<<(NN * 32 + 255) / 256, 256>>>(x);
    k_gemm_fused<<<(NN + 63) / 64, 256>>>(W1, b1, out, 1);

    // layer 2: gather-aggregate h over [0,UU), fused GEMM -> out head
    k_agg2<<<(UU * 32 + 255) / 256, 256>>>();
    k_gemm_fused<<<(UU + 63) / 64, 256>>>(W2, b2, out, 2);
}

// round 15
// speedup vs baseline: 1.0707x; 1.0707x over previous
#include <cuda_runtime.h>
#include <cuda_bf16.h>
#include <math.h>
#include <limits.h>

#define NN 100000
#define EE 3200000
#define FF 128
#define UU 1000
#define DETECT_N 262144

#define FMA_F32X2(d, a, b, c) \
    asm("fma.rn.f32x2 %0, %1, %2, %3;" : "=l"(d) : "l"(a), "l"(b), "l"(c))
#define PACK2_F32(out, v) \
    asm("mov.b64 %0, {%1, %1};" : "=l"(out) : "r"(v))

// Scratch (device globals) — referenced ONLY inside kernels (never as launch args!)
__device__ float          g_A  [(long long)NN * FF];
__device__ float          g_H  [(long long)NN * FF];
__device__ __nv_bfloat16  g_Xh [(long long)NN * FF];
__device__ float g_inv[NN];
__device__ int   g_deg[NN];
__device__ int   g_mask[NN];
__device__ int   g_list[NN];
__device__ int   g_off[NN];
__device__ int   g_cur[NN];   // pre-initialized to off for masked nodes
__device__ int   g_csr[EE];
__device__ int   g_cnt;
__device__ int   g_total;
__device__ int   g_is32;      // monotonic: set once, never reset

__device__ __forceinline__ int edge_at(const void* p, long long i) {
    return g_is32 ? ((const int*)p)[i] : (int)((const long long*)p)[i];
}

__device__ __forceinline__ int2 edge_pair(const void* p, long long i2) {
    if (g_is32) {
        return ((const int2*)p)[i2];
    } else {
        longlong2 v = ((const longlong2*)p)[i2];
        return make_int2((int)v.x, (int)v.y);
    }
}

// ---------------------------------------------------------------------------
// setup: bf16 conversion of x + DIRECT tail write to out (x is read once)
// + per-node init + dtype detect. grid = NN*FF/4/256 = 12800 blocks.
__global__ void k_setup(const float* __restrict__ x, float* __restrict__ out,
                        const int* __restrict__ e32) {
    long long i = (long long)blockIdx.x * 256 + threadIdx.x;
    float4 v = ((const float4*)x)[i];
    __nv_bfloat162 a = __floats2bfloat162_rn(v.x, v.y);
    __nv_bfloat162 b = __floats2bfloat162_rn(v.z, v.w);
    uint2 u; u.x = *(unsigned*)&a; u.y = *(unsigned*)&b;
    ((uint2*)g_Xh)[i] = u;
    // passthrough rows [UU, NN): out tail = x tail, written from same registers
    if (i >= (long long)UU * FF / 4) ((float4*)out)[i] = v;
    if (i < NN) {
        g_deg[i] = 0;
        g_mask[i] = (i < UU) ? 1 : 0;
    }
    if (i == 0) { g_cnt = 0; g_total = 0; }
    if (i < DETECT_N && e32[2 * i + 1] != 0) g_is32 = 1;
}

// deg+mask: 2 edges per thread, dst column only; src fetched lazily (~1%).
__global__ void k_deg_mask(const void* __restrict__ eS, const void* __restrict__ eD,
                           long long dOff2) {
    int t = blockIdx.x * 256 + threadIdx.x;
    if (t >= EE / 2) return;
    int2 d = edge_pair(eD, dOff2 + t);
    if ((unsigned)d.x < NN) {
        atomicAdd(&g_deg[d.x], 1);
        if (d.x < UU) {
            int src = edge_at(eS, 2LL * t);
            if ((unsigned)src < NN) g_mask[src] = 1;
        }
    }
    if ((unsigned)d.y < NN) {
        atomicAdd(&g_deg[d.y], 1);
        if (d.y < UU) {
            int src = edge_at(eS, 2LL * t + 1);
            if ((unsigned)src < NN) g_mask[src] = 1;
        }
    }
}

// inv-sqrt + compact + bucket allocation (warp-aggregated atomics)
// + fused cursor init (cur = off for masked nodes).
__global__ void k_inv_compact() {
    int i = blockIdx.x * 256 + threadIdx.x;
    int lane = threadIdx.x & 31;
    bool inb = (i < NN);
    int d = inb ? g_deg[i] : 0;
    if (inb) g_inv[i] = rsqrtf((float)d + 1.0f);
    bool active = inb && g_mask[i];
    unsigned ballot = __ballot_sync(0xFFFFFFFFu, active);
    int total = __popc(ballot);
    int myidx = __popc(ballot & ((1u << lane) - 1));
    int dv = active ? d : 0;
    int v = dv;
    #pragma unroll
    for (int o = 1; o < 32; o <<= 1) {
        int t = __shfl_up_sync(0xFFFFFFFFu, v, o);
        if (lane >= o) v += t;
    }
    int excl = v - dv;
    int wsum = __shfl_sync(0xFFFFFFFFu, v, 31);
    int baseCnt = 0, baseOff = 0;
    if (total > 0 && lane == 0) {
        baseCnt = atomicAdd(&g_cnt, total);
        baseOff = atomicAdd(&g_total, wsum);
    }
    baseCnt = __shfl_sync(0xFFFFFFFFu, baseCnt, 0);
    baseOff = __shfl_sync(0xFFFFFFFFu, baseOff, 0);
    if (active) {
        int off = baseOff + excl;
        g_list[baseCnt + myidx] = i;
        g_off[i] = off;
        g_cur[i] = off;
    }
}

// fill: mask-gated single atomic (cur pre-initialized to off).
__global__ void k_fill(const void* __restrict__ eS, const void* __restrict__ eD,
                       long long dOff2) {
    int t = blockIdx.x * 256 + threadIdx.x;
    if (t >= EE / 2) return;
    int2 d = edge_pair(eD, dOff2 + t);
    if ((unsigned)d.x < NN && g_mask[d.x]) {
        int pos = atomicAdd(&g_cur[d.x], 1);
        if ((unsigned)pos < EE) {
            int src = edge_at(eS, 2LL * t);
            g_csr[pos] = ((unsigned)src < NN) ? src : 0;
        }
    }
    if ((unsigned)d.y < NN && g_mask[d.y]) {
        int pos = atomicAdd(&g_cur[d.y], 1);
        if ((unsigned)pos < EE) {
            int src = edge_at(eS, 2LL * t + 1);
            g_csr[pos] = ((unsigned)src < NN) ? src : 0;
        }
    }
}

// ---------------------------------------------------------------------------
// Layer-1 aggregation: warp per compact row; bf16 uint2 gathers, fp32 accum.
__device__ __forceinline__ void bf16_fma(float4& acc, float c, uint2 u) {
    float2 f0 = __bfloat1622float2(*(__nv_bfloat162*)&u.x);
    float2 f1 = __bfloat1622float2(*(__nv_bfloat162*)&u.y);
    acc.x += c * f0.x; acc.y += c * f0.y;
    acc.z += c * f1.x; acc.w += c * f1.y;
}

__global__ void k_agg1(const float* __restrict__ x) {
    int w = (blockIdx.x * 256 + threadIdx.x) >> 5;
    int lane = threadIdx.x & 31;
    if (w >= g_cnt) return;
    int row = g_list[w];
    float invr = g_inv[row];
    float4 acc = ((const float4*)(x + (long long)row * FF))[lane];
    float s = invr * invr;
    acc.x *= s; acc.y *= s; acc.z *= s; acc.w *= s;
    int beg = g_off[row], end = beg + g_deg[row];
    int j = beg;
    for (; j + 4 <= end; j += 4) {
        int s0 = g_csr[j], s1 = g_csr[j + 1], s2 = g_csr[j + 2], s3 = g_csr[j + 3];
        float c0 = g_inv[s0] * invr, c1 = g_inv[s1] * invr;
        float c2 = g_inv[s2] * invr, c3 = g_inv[s3] * invr;
        uint2 u0 = *(const uint2*)(g_Xh + (long long)s0 * FF + lane * 4);
        uint2 u1 = *(const uint2*)(g_Xh + (long long)s1 * FF + lane * 4);
        uint2 u2 = *(const uint2*)(g_Xh + (long long)s2 * FF + lane * 4);
        uint2 u3 = *(const uint2*)(g_Xh + (long long)s3 * FF + lane * 4);
        bf16_fma(acc, c0, u0); bf16_fma(acc, c1, u1);
        bf16_fma(acc, c2, u2); bf16_fma(acc, c3, u3);
    }
    for (; j < end; j++) {
        int src = g_csr[j];
        float c = g_inv[src] * invr;
        uint2 u = *(const uint2*)(g_Xh + (long long)src * FF + lane * 4);
        bf16_fma(acc, c, u);
    }
    ((float4*)(g_A + (long long)row * FF))[lane] = acc;
}

// Layer-2 aggregation: warp per dst row < UU; fp32 (tiny).
__global__ void k_agg2() {
    int w = (blockIdx.x * 256 + threadIdx.x) >> 5;
    int lane = threadIdx.x & 31;
    if (w >= UU) return;
    int row = w;
    float invr = g_inv[row];
    float4 acc = ((const float4*)(g_H + (long long)row * FF))[lane];
    float s = invr * invr;
    acc.x *= s; acc.y *= s; acc.z *= s; acc.w *= s;
    int beg = g_off[row], end = beg + g_deg[row];
    int j = beg;
    for (; j + 2 <= end; j += 2) {
        int s0 = g_csr[j], s1 = g_csr[j + 1];
        float c0 = g_inv[s0] * invr, c1 = g_inv[s1] * invr;
        float4 v0 = ((const float4*)(g_H + (long long)s0 * FF))[lane];
        float4 v1 = ((const float4*)(g_H + (long long)s1 * FF))[lane];
        acc.x += c0 * v0.x + c1 * v1.x;
        acc.y += c0 * v0.y + c1 * v1.y;
        acc.z += c0 * v0.z + c1 * v1.z;
        acc.w += c0 * v0.w + c1 * v1.w;
    }
    for (; j < end; j++) {
        int src = g_csr[j];
        float c = g_inv[src] * invr;
        float4 v = ((const float4*)(g_H + (long long)src * FF))[lane];
        acc.x += c * v.x; acc.y += c * v.y; acc.z += c * v.z; acc.w += c * v.w;
    }
    ((float4*)(g_A + (long long)row * FF))[lane] = acc;
}

// ---------------------------------------------------------------------------
// Fused GEMM + bias + ELU: 64 rows/block, 4x8 tile, FFMA2 (f32x2) mainloop.
__global__ void k_gemm_fused(const float* __restrict__ W, const float* __restrict__ bias,
                             float* __restrict__ outp, int layer) {
    __shared__ float Ws[32 * 128];
    __shared__ float XsT[32 * 68];
    __shared__ int   rlist[64];
    __shared__ int   s_n;

    int tid = threadIdx.x;
    if (tid == 0) s_n = (layer == 1) ? g_cnt : UU;
    __syncthreads();
    int n = s_n;
    int base = blockIdx.x * 64;
    if (base >= n) return;

    if (tid < 64) {
        int gr = base + tid;
        rlist[tid] = (gr < n) ? ((layer == 1) ? g_list[gr] : gr) : -1;
    }
    float* O = (layer == 1) ? g_H : outp;

    int tx = tid & 15, ty = tid >> 4;
    unsigned long long acc2[4][4];
    #pragma unroll
    for (int i = 0; i < 4; i++)
        #pragma unroll
        for (int j = 0; j < 4; j++) acc2[i][j] = 0ULL;
    __syncthreads();

    for (int kc = 0; kc < 128; kc += 32) {
        #pragma unroll 4
        for (int idx = tid; idx < 4096; idx += 256)
            Ws[idx] = W[(kc + (idx >> 7)) * 128 + (idx & 127)];
        #pragma unroll 4
        for (int idx = tid; idx < 2048; idx += 256) {
            int r = idx >> 5, c = idx & 31;
            int grow = rlist[r];
            XsT[c * 68 + r] = (grow >= 0) ? g_A[(long long)grow * FF + kc + c] : 0.0f;
        }
        __syncthreads();

        #pragma unroll
        for (int k = 0; k < 32; k++) {
            float4 a = *(const float4*)&XsT[k * 68 + ty * 4];
            ulonglong2 w0 = *(const ulonglong2*)&Ws[k * 128 + tx * 4];
            ulonglong2 w1 = *(const ulonglong2*)&Ws[k * 128 + 64 + tx * 4];
            unsigned long long bv2[4] = {w0.x, w0.y, w1.x, w1.y};
            unsigned au[4] = {__float_as_uint(a.x), __float_as_uint(a.y),
                              __float_as_uint(a.z), __float_as_uint(a.w)};
            #pragma unroll
            for (int i = 0; i < 4; i++) {
                unsigned long long a2;
                PACK2_F32(a2, au[i]);
                #pragma unroll
                for (int j = 0; j < 4; j++)
                    FMA_F32X2(acc2[i][j], a2, bv2[j], acc2[i][j]);
            }
        }
        __syncthreads();
    }

    float bj[8];
    #pragma unroll
    for (int q = 0; q < 4; q++) {
        bj[q]     = __ldg(&bias[tx * 4 + q]);
        bj[4 + q] = __ldg(&bias[64 + tx * 4 + q]);
    }

    #pragma unroll
    for (int i = 0; i < 4; i++) {
        int gr = base + ty * 4 + i;
        if (gr < n) {
            int grow = rlist[ty * 4 + i];
            float* o = O + (long long)grow * FF;
            float r0[4], r1[4];
            #pragma unroll
            for (int j = 0; j < 4; j++) {
                unsigned lo, hi;
                asm("mov.b64 {%0, %1}, %2;" : "=r"(lo), "=r"(hi) : "l"(acc2[i][j]));
                float e0 = __uint_as_float(lo), e1 = __uint_as_float(hi);
                if (j < 2) {
                    float v = e0 + bj[2 * j];
                    r0[2 * j] = (v > 0.0f) ? v : expm1f(v);
                    v = e1 + bj[2 * j + 1];
                    r0[2 * j + 1] = (v > 0.0f) ? v : expm1f(v);
                } else {
                    float v = e0 + bj[2 * j];
                    r1[2 * (j - 2)] = (v > 0.0f) ? v : expm1f(v);
                    v = e1 + bj[2 * j + 1];
                    r1[2 * (j - 2) + 1] = (v > 0.0f) ? v : expm1f(v);
                }
            }
            *(float4*)&o[tx * 4]      = *(float4*)&r0[0];
            *(float4*)&o[64 + tx * 4] = *(float4*)&r1[0];
        }
    }
}

// ---------------------------------------------------------------------------
extern "C" void kernel_launch(void* const* d_in, const int* in_sizes, int n_in,
                              void* d_out, int out_size) {
    const float *x = 0, *W1 = 0, *b1 = 0, *W2 = 0, *b2 = 0;
    const void *eA = 0, *eB = 0;
    long long dOff = 0;
    for (int i = 0; i < n_in; i++) {
        long long s = in_sizes[i];
        if (s == (long long)NN * FF)      x = (const float*)d_in[i];
        else if (s == 2LL * EE)           eA = d_in[i];
        else if (s == (long long)EE)     { if (!eA) eA = d_in[i]; else eB = d_in[i]; }
        else if (s == FF * FF)           { if (!W1) W1 = (const float*)d_in[i];
                                           else     W2 = (const float*)d_in[i]; }
        else if (s == FF)                { if (!b1) b1 = (const float*)d_in[i];
                                           else     b2 = (const float*)d_in[i]; }
    }
    if (!eB) { eB = eA; dOff = EE; }
    float* out = (float*)d_out;
    long long dOff2 = dOff / 2;

    const int e2grid = (EE / 2 + 255) / 256;
    const int ngrid = (NN + 255) / 256;

    // setup (bf16 convert + out-tail write + node init + detect) + CSR
    k_setup<<<(NN * FF / 4) / 256, 256>>>(x, out, (const int*)eA);
    k_deg_mask<<<e2grid, 256>>>(eA, eB, dOff2);
    k_inv_compact<<<ngrid, 256>>>();
    k_fill<<<e2grid, 256>>>(eA, eB, dOff2);

    // layer 1: bf16 gather-aggregate over S, fused GEMM+bias+ELU -> g_H
    k_agg1<<<(NN * 32 + 255) / 256, 256>>>(x);
    k_gemm_fused<<<(NN + 63) / 64, 256>>>(W1, b1, out, 1);

    // layer 2: gather-aggregate h over [0,UU), fused GEMM -> out head
    k_agg2<<<(UU * 32 + 255) / 256, 256>>>();
    k_gemm_fused<<<(UU + 63) / 64, 256>>>(W2, b2, out, 2);
}